// round 15
// baseline (speedup 1.0000x reference)
#include <cuda_runtime.h>
#include <math.h>

// Problem shape (fixed for this benchmark instance)
#define BB 16
#define TT 2048
#define DD 1024
#define NROW (BB*TT)
#define KCH 4              // output rows per gather block
#define NCH 8              // scan segments per batch
#define CHT (TT/NCH)       // 256 timesteps per segment
#define CBLK (CHT/8)       // 32 alpha blocks per (batch, chunk)

// Scratch (device globals; no allocation allowed)
__device__ float  g_alphas[NROW];
__device__ float2 g_ev[NROW];             // {cur, t_bits} per fire, packed per batch
__device__ int    g_nf[BB];
__device__ float2 g_carry[BB * NCH];      // {integ, nf_bits} after segment c
__device__ double g_psum[BB * NCH];       // per-segment alpha sums
__device__ int    g_cnt[BB * NCH * 32];   // one counter per 128B line; self-resetting

// ---------------- Fused: alphas (t-chunk-major) + chained elected scan segments.
// Election rule: slot (b,c) needs CBLK alpha arrivals (+1 carry arrival for c>0);
// the LAST arriver — alpha block or predecessor runner — executes the segment.
// Fire arithmetic bit-identical to the reference:
//   s = integ + a; fire = s > 0.95f;
//   cur = fire ? (1 - integ) : a; integ = fire ? s - 1.0f : s  (Sterbenz-exact)
__global__ void __launch_bounds__(256) k_fused(const float* __restrict__ hs,
                                               const float* __restrict__ mask,
                                               const float* __restrict__ w,
                                               const float* __restrict__ bias,
                                               float* __restrict__ omask) {
    __shared__ float  s_al[CHT];          // 1 KB
    __shared__ float2 s_ev[CHT];          // 2 KB
    __shared__ double s_part[CHT/4];      // 512 B
    __shared__ float2 s_carry;
    __shared__ int    s_elected;
    __shared__ int    s_nf;
    __shared__ int    s_len;

    const int bid  = blockIdx.x;          // 4096 blocks: chunk-major
    const int tid  = threadIdx.x;
    const int wid  = tid >> 5;
    const int lane = tid & 31;

    const int chunk  = bid >> 9;          // 512 blocks per chunk
    const int within = bid & 511;
    const int b      = within >> 5;       // CBLK=32 blocks per (batch, chunk)
    const int tblk   = within & 31;

    // ---- alphas for this block's 8 rows (one row per warp) ----
    {
        int row = b * TT + chunk * CHT + tblk * 8 + wid;
        const float4* r4 = reinterpret_cast<const float4*>(hs + (size_t)row * DD);
        const float4* w4 = reinterpret_cast<const float4*>(w);

        float acc = 0.0f;
#pragma unroll
        for (int i = 0; i < 8; i++) {
            float4 h  = r4[lane + 32 * i];
            float4 ww = __ldg(&w4[lane + 32 * i]);
            acc = fmaf(h.x, ww.x, acc);
            acc = fmaf(h.y, ww.y, acc);
            acc = fmaf(h.z, ww.z, acc);
            acc = fmaf(h.w, ww.w, acc);
        }
#pragma unroll
        for (int o = 16; o > 0; o >>= 1)
            acc += __shfl_down_sync(0xffffffffu, acc, o);

        if (lane == 0) {
            float x = acc + bias[0];
            float s = 1.0f / (1.0f + expf(-x));
            g_alphas[row] = s * mask[row];
        }
    }
    __syncthreads();

    // ---- initial election: last arriver on this (b, chunk) slot ----
    if (tid == 0) {
        __threadfence();                               // release our alphas
        int need = (chunk == 0) ? (CBLK - 1) : CBLK;
        int old = atomicAdd(&g_cnt[(b * NCH + chunk) * 32], 1);
        s_elected = (old == need);
    }
    __syncthreads();
    if (!s_elected) return;

    // ================= segment-chaining runner =================
    int chunk_run = chunk;
    for (;;) {
        const int slot = b * NCH + chunk_run;

        // acquire producers' writes (alphas, carry, psums)
        if (tid == 0) {
            __threadfence();
            float2 c;
            if (chunk_run > 0) c = g_carry[slot - 1];
            else               c = make_float2(0.0f, __int_as_float(0));
            s_carry = c;
        }
        __syncthreads();
        const float integ0 = s_carry.x;
        const int   nf_in  = __float_as_int(s_carry.y);

        // stage this segment's CHT alphas into smem + per-thread partial sums
        const float4* al4 = reinterpret_cast<const float4*>(g_alphas + b * TT + chunk_run * CHT);
        float4* s4 = reinterpret_cast<float4*>(s_al);
        if (tid < CHT / 4) {
            float4 v = al4[tid];
            s4[tid] = v;
            s_part[tid] = (double)v.x + v.y + v.z + v.w;
        }
        __syncthreads();

        if (wid == 0) {
            if (tid == 0) {
                // -------- serial scan of CHT steps (from smem) --------
                float integ = integ0;
                int nfseg = 0;
                float4 pa = s4[0], pb = s4[1];
                for (int t0 = 0; t0 < CHT; t0 += 8) {
                    float buf[8];
                    buf[0] = pa.x; buf[1] = pa.y; buf[2] = pa.z; buf[3] = pa.w;
                    buf[4] = pb.x; buf[5] = pb.y; buf[6] = pb.z; buf[7] = pb.w;
                    if (t0 + 8 < CHT) {
                        pa = s4[(t0 >> 2) + 2];
                        pb = s4[(t0 >> 2) + 3];
                    }
#pragma unroll
                    for (int j = 0; j < 8; j++) {
                        float a = buf[j];
                        float dist = 1.0f - integ;      // off critical path
                        float s = integ + a;            // FADD — critical
                        float s1 = s - 1.0f;            // off critical path (Sterbenz-exact)
                        float2 e;
                        e.x = dist;                                       // cur at fire
                        e.y = __int_as_float(chunk_run * CHT + t0 + j);   // fire time
                        s_ev[nfseg] = e;                                  // STS.64
                        int finc;
                        // setp.gt (4, pred-as-data) + selp (4): 12-cy total chain
                        asm("{\n\t"
                            ".reg .pred p;\n\t"
                            "setp.gt.f32 p, %2, 0f3F733333;\n\t"   // s > 0.95f
                            "selp.f32 %0, %3, %2, p;\n\t"          // integ = fire ? s-1 : s
                            "selp.s32 %1, 1, 0, p;\n\t"
                            "}"
                            : "=f"(integ), "=r"(finc) : "f"(s), "f"(s1));
                        nfseg += finc;
                    }
                }
                s_nf = nfseg;
                s_carry.x = integ;                      // pass out to epilogue
            }
        } else {
            if (wid == 1) {
                // segment partial sum (concurrent with scan)
                double r = s_part[lane] + s_part[lane + 32];
#pragma unroll
                for (int o = 16; o > 0; o >>= 1)
                    r += __shfl_down_sync(0xffffffffu, r, o);
                if (lane == 0) {
                    g_psum[slot] = r;
                    if (chunk_run == NCH - 1) {
                        double tot = r;
#pragma unroll
                        for (int c = 0; c < NCH - 1; c++)
                            tot += g_psum[b * NCH + c];
                        float fsum = (float)tot;
                        s_len = (int)rintf(fsum);   // round-half-to-even like jnp.round
                    }
                }
            }
            if (chunk_run == NCH - 1) {
                // warps 1-7 sync among themselves; write mask while warp 0 scans
                asm volatile("bar.sync 1, 224;" ::: "memory");
                int len = s_len;
                float4* om4 = reinterpret_cast<float4*>(omask + b * TT);
                for (int i = tid - 32; i < TT / 4; i += 224) {
                    int k = i * 4;
                    float4 m;
                    m.x = (k + 0 < len) ? 1.0f : 0.0f;
                    m.y = (k + 1 < len) ? 1.0f : 0.0f;
                    m.z = (k + 2 < len) ? 1.0f : 0.0f;
                    m.w = (k + 3 < len) ? 1.0f : 0.0f;
                    om4[i] = m;
                }
            }
        }
        __syncthreads();

        // -------- coalesced event flush at offset nf_in --------
        const int nf = s_nf;
        float2* ev = g_ev + b * TT + nf_in;
        for (int i = tid; i < nf; i += 256)
            ev[i] = s_ev[i];
        __syncthreads();

        // -------- epilogue: carry hand-off + (possible) self-election --------
        if (tid == 0) {
            if (chunk_run < NCH - 1) {
                float2 carry;
                carry.x = s_carry.x;                       // final integ of this segment
                carry.y = __int_as_float(nf_in + nf);
                g_carry[slot] = carry;
                __threadfence();                           // release carry+events+psum
                int old = atomicAdd(&g_cnt[(slot + 1) * 32], 1);
                s_elected = (old == CBLK);                 // (CBLK+1)-th arrival wins
            } else {
                g_nf[b] = nf_in + nf;
                s_elected = 0;
            }
            g_cnt[slot * 32] = 0;                          // self-reset (all arrivals done)
        }
        __syncthreads();
        if (!s_elected) return;
        chunk_run++;
    }
}

// ---------------- Phase 3: gather — KCH consecutive output rows per block.
// Reverse-ordered so first-scheduled blocks read the hs rows most recently
// touched by k_fused (still L2-resident).
__global__ void k_gather(const float* __restrict__ hs,
                         float* __restrict__ out) {
    int b   = (BB - 1) - blockIdx.y;                    // reversed batch order
    int k0  = (TT / KCH - 1 - blockIdx.x) * KCH;        // reversed k order
    int tid = threadIdx.x;            // 256 threads, 4 floats each
    const int base = b * TT;

    int nf = g_nf[b];
    const float4 zero = make_float4(0.f, 0.f, 0.f, 0.f);

    if (k0 >= nf) {
#pragma unroll
        for (int k = k0; k < k0 + KCH; k++)
            reinterpret_cast<float4*>(out + ((size_t)(base + k)) * DD)[tid] = zero;
        return;
    }

    int klast = (k0 + KCH < nf) ? (k0 + KCH) : nf;

    float4 acc = zero;
    int tprev = -1;

    if (k0 > 0) {
        float2 evp = g_ev[base + k0 - 1];
        tprev = __float_as_int(evp.y);
        float r = g_alphas[base + tprev] - evp.x;   // resid = a - cur
        const float4* h = reinterpret_cast<const float4*>(hs + ((size_t)(base + tprev)) * DD);
        float4 v = h[tid];
        acc.x = r * v.x; acc.y = r * v.y; acc.z = r * v.z; acc.w = r * v.w;
    }

    for (int k = k0; k < klast; k++) {
        float2 ev = g_ev[base + k];
        int tend = __float_as_int(ev.y);

        // interior rows: coefficient == alpha
        for (int t = tprev + 1; t < tend; t++) {
            float c = g_alphas[base + t];
            const float4* h = reinterpret_cast<const float4*>(hs + ((size_t)(base + t)) * DD);
            float4 v = h[tid];
            acc.x = fmaf(c, v.x, acc.x);
            acc.y = fmaf(c, v.y, acc.y);
            acc.z = fmaf(c, v.z, acc.z);
            acc.w = fmaf(c, v.w, acc.w);
        }

        // fire row: finish this output row, then seed the next with the residual
        const float4* h = reinterpret_cast<const float4*>(hs + ((size_t)(base + tend)) * DD);
        float4 v = h[tid];
        float cur = ev.x;
        acc.x = fmaf(cur, v.x, acc.x);
        acc.y = fmaf(cur, v.y, acc.y);
        acc.z = fmaf(cur, v.z, acc.z);
        acc.w = fmaf(cur, v.w, acc.w);
        reinterpret_cast<float4*>(out + ((size_t)(base + k)) * DD)[tid] = acc;

        float r = g_alphas[base + tend] - cur;      // resid = a - cur
        acc.x = r * v.x; acc.y = r * v.y; acc.z = r * v.z; acc.w = r * v.w;
        tprev = tend;
    }

    for (int k = klast; k < k0 + KCH; k++)
        reinterpret_cast<float4*>(out + ((size_t)(base + k)) * DD)[tid] = zero;
}

extern "C" void kernel_launch(void* const* d_in, const int* in_sizes, int n_in,
                              void* d_out, int out_size) {
    const float* hs   = (const float*)d_in[0];   // [B,T,D]
    const float* mask = (const float*)d_in[1];   // [B,1,T]
    const float* w    = (const float*)d_in[2];   // [D]
    const float* bias = (const float*)d_in[3];   // scalar

    float* out   = (float*)d_out;                           // [B,T,D]
    float* omask = (float*)d_out + (size_t)BB * TT * DD;    // [B,1,T] as 0/1 floats

    // Fused: alphas (t-chunk-major) + chained scan segments + lens/mask
    k_fused<<<NROW / 8, 256>>>(hs, mask, w, bias, omask);
    // Phase 3: KCH output rows per block, reverse-ordered for L2 reuse
    {
        dim3 grid(TT / KCH, BB);
        k_gather<<<grid, 256>>>(hs, out);
    }
}

// round 17
// speedup vs baseline: 1.0254x; 1.0254x over previous
#include <cuda_runtime.h>
#include <math.h>

// Problem shape (fixed for this benchmark instance)
#define BB 16
#define TT 2048
#define DD 1024
#define NROW (BB*TT)
#define KCH 4              // output rows per gather block
#define NCH 4              // scan segments per batch
#define CHT (TT/NCH)       // 512 timesteps per segment
#define CBLK (CHT/8)       // 64 alpha blocks per (batch, chunk)

// Scratch (device globals; no allocation allowed)
__device__ float  g_alphas[NROW];
__device__ float2 g_ev[NROW];             // {cur, t_bits} per fire, packed per batch
__device__ int    g_nf[BB];
__device__ int    g_cnt[BB * NCH * 32];   // one counter per 128B line; self-resetting

// ---------------- Fused: alphas (t-chunk-major) + one persistent runner block
// per batch (elected as last arriver of chunk 0) that scans all 4 segments,
// spin-waiting briefly on each later chunk's alpha counter (max 16 spinners).
// Fire arithmetic bit-identical to the reference:
//   s = integ + a; fire = s > 0.95f;
//   cur = fire ? (1 - integ) : a; integ = fire ? s - 1.0f : s  (Sterbenz-exact)
__global__ void __launch_bounds__(256) k_fused(const float* __restrict__ hs,
                                               const float* __restrict__ mask,
                                               const float* __restrict__ w,
                                               const float* __restrict__ bias,
                                               float* __restrict__ omask) {
    __shared__ float  s_al[CHT];          // 2 KB
    __shared__ float2 s_ev[CHT];          // 4 KB
    __shared__ double s_part[CHT/4];      // 1 KB
    __shared__ double s_sum;
    __shared__ int    s_elected;
    __shared__ int    s_nf;
    __shared__ int    s_base;

    const int bid  = blockIdx.x;          // 4096 blocks: chunk-major
    const int tid  = threadIdx.x;
    const int wid  = tid >> 5;
    const int lane = tid & 31;

    const int chunk  = bid >> 10;         // 1024 blocks per chunk
    const int within = bid & 1023;
    const int b      = within >> 6;       // CBLK=64 blocks per (batch, chunk)
    const int tblk   = within & 63;

    // ---- alphas for this block's 8 rows (one row per warp) ----
    {
        int row = b * TT + chunk * CHT + tblk * 8 + wid;
        const float4* r4 = reinterpret_cast<const float4*>(hs + (size_t)row * DD);
        const float4* w4 = reinterpret_cast<const float4*>(w);

        float acc = 0.0f;
#pragma unroll
        for (int i = 0; i < 8; i++) {
            float4 h  = r4[lane + 32 * i];
            float4 ww = __ldg(&w4[lane + 32 * i]);
            acc = fmaf(h.x, ww.x, acc);
            acc = fmaf(h.y, ww.y, acc);
            acc = fmaf(h.z, ww.z, acc);
            acc = fmaf(h.w, ww.w, acc);
        }
#pragma unroll
        for (int o = 16; o > 0; o >>= 1)
            acc += __shfl_down_sync(0xffffffffu, acc, o);

        if (lane == 0) {
            float x = acc + bias[0];
            float s = 1.0f / (1.0f + expf(-x));
            g_alphas[row] = s * mask[row];
        }
    }
    __syncthreads();

    // ---- arrival + (chunk 0 only) runner election ----
    if (tid == 0) {
        __threadfence();                               // release our alphas
        int old = atomicAdd(&g_cnt[(b * NCH + chunk) * 32], 1);
        s_elected = (chunk == 0) && (old == CBLK - 1);
    }
    __syncthreads();
    if (!s_elected) return;

    // ================= persistent runner: all NCH segments =================
    if (tid == 0) { s_sum = 0.0; s_base = 0; }
    float integ = 0.0f;                   // lives in tid0's registers across chunks

    for (int c = 0; c < NCH; c++) {
        // wait for this chunk's alphas (c=0 already complete by election)
        if (tid == 0) {
            volatile int* p = &g_cnt[(b * NCH + c) * 32];
            while (*p != CBLK) __nanosleep(64);
            __threadfence();                           // acquire producers' alphas
            g_cnt[(b * NCH + c) * 32] = 0;             // consumed; graph-replay reset
        }
        __syncthreads();

        // stage this segment's CHT alphas into smem + per-thread partial sums
        const float4* al4 = reinterpret_cast<const float4*>(g_alphas + b * TT + c * CHT);
        float4* s4 = reinterpret_cast<float4*>(s_al);
        if (tid < CHT / 4) {
            float4 v = al4[tid];
            s4[tid] = v;
            s_part[tid] = (double)v.x + v.y + v.z + v.w;
        }
        __syncthreads();

        if (tid == 0) {
            // -------- serial scan of CHT steps (from smem) --------
            int nfseg = 0;
            float4 pa = s4[0], pb = s4[1];
            for (int t0 = 0; t0 < CHT; t0 += 8) {
                float buf[8];
                buf[0] = pa.x; buf[1] = pa.y; buf[2] = pa.z; buf[3] = pa.w;
                buf[4] = pb.x; buf[5] = pb.y; buf[6] = pb.z; buf[7] = pb.w;
                if (t0 + 8 < CHT) {
                    pa = s4[(t0 >> 2) + 2];
                    pb = s4[(t0 >> 2) + 3];
                }
#pragma unroll
                for (int j = 0; j < 8; j++) {
                    float a = buf[j];
                    float dist = 1.0f - integ;      // off critical path
                    float s = integ + a;            // FADD — critical
                    float s1 = s - 1.0f;            // off critical path (Sterbenz-exact)
                    float2 e;
                    e.x = dist;                                // cur at fire
                    e.y = __int_as_float(c * CHT + t0 + j);    // fire time
                    s_ev[nfseg] = e;                           // STS.64
                    int finc;
                    // setp.gt (4, pred-as-data) + selp (4): 12-cy chain
                    asm("{\n\t"
                        ".reg .pred p;\n\t"
                        "setp.gt.f32 p, %2, 0f3F733333;\n\t"   // s > 0.95f
                        "selp.f32 %0, %3, %2, p;\n\t"          // integ = fire ? s-1 : s
                        "selp.s32 %1, 1, 0, p;\n\t"
                        "}"
                        : "=f"(integ), "=r"(finc) : "f"(s), "f"(s1));
                    nfseg += finc;
                }
            }
            s_nf = nfseg;
        } else if (wid == 1) {
            // segment partial sum (concurrent with scan)
            double r = s_part[lane] + s_part[lane + 32]
                     + s_part[lane + 64] + s_part[lane + 96];
#pragma unroll
            for (int o = 16; o > 0; o >>= 1)
                r += __shfl_down_sync(0xffffffffu, r, o);
            if (lane == 0) s_sum += r;      // sole writer between barriers
        }
        __syncthreads();

        // -------- coalesced event flush at offset s_base --------
        const int nf   = s_nf;
        const int base = s_base;
        float2* ev = g_ev + b * TT + base;
        for (int i = tid; i < nf; i += 256)
            ev[i] = s_ev[i];
        __syncthreads();
        if (tid == 0) s_base = base + nf;
        __syncthreads();
    }

    // -------- finale: nf, length, mask --------
    if (tid == 0) g_nf[b] = s_base;
    int len = (int)rintf((float)s_sum);     // round-half-to-even like jnp.round
    float4* om4 = reinterpret_cast<float4*>(omask + b * TT);
    for (int i = tid; i < TT / 4; i += 256) {
        int k = i * 4;
        float4 m;
        m.x = (k + 0 < len) ? 1.0f : 0.0f;
        m.y = (k + 1 < len) ? 1.0f : 0.0f;
        m.z = (k + 2 < len) ? 1.0f : 0.0f;
        m.w = (k + 3 < len) ? 1.0f : 0.0f;
        om4[i] = m;
    }
}

// ---------------- Phase 3: gather — KCH consecutive output rows per block.
// Reverse-ordered so first-scheduled blocks read the hs rows most recently
// touched by k_fused (still L2-resident).
__global__ void k_gather(const float* __restrict__ hs,
                         float* __restrict__ out) {
    int b   = (BB - 1) - blockIdx.y;                    // reversed batch order
    int k0  = (TT / KCH - 1 - blockIdx.x) * KCH;        // reversed k order
    int tid = threadIdx.x;            // 256 threads, 4 floats each
    const int base = b * TT;

    int nf = g_nf[b];
    const float4 zero = make_float4(0.f, 0.f, 0.f, 0.f);

    if (k0 >= nf) {
#pragma unroll
        for (int k = k0; k < k0 + KCH; k++)
            reinterpret_cast<float4*>(out + ((size_t)(base + k)) * DD)[tid] = zero;
        return;
    }

    int klast = (k0 + KCH < nf) ? (k0 + KCH) : nf;

    float4 acc = zero;
    int tprev = -1;

    if (k0 > 0) {
        float2 evp = g_ev[base + k0 - 1];
        tprev = __float_as_int(evp.y);
        float r = g_alphas[base + tprev] - evp.x;   // resid = a - cur
        const float4* h = reinterpret_cast<const float4*>(hs + ((size_t)(base + tprev)) * DD);
        float4 v = h[tid];
        acc.x = r * v.x; acc.y = r * v.y; acc.z = r * v.z; acc.w = r * v.w;
    }

    for (int k = k0; k < klast; k++) {
        float2 ev = g_ev[base + k];
        int tend = __float_as_int(ev.y);

        // interior rows: coefficient == alpha
        for (int t = tprev + 1; t < tend; t++) {
            float c = g_alphas[base + t];
            const float4* h = reinterpret_cast<const float4*>(hs + ((size_t)(base + t)) * DD);
            float4 v = h[tid];
            acc.x = fmaf(c, v.x, acc.x);
            acc.y = fmaf(c, v.y, acc.y);
            acc.z = fmaf(c, v.z, acc.z);
            acc.w = fmaf(c, v.w, acc.w);
        }

        // fire row: finish this output row, then seed the next with the residual
        const float4* h = reinterpret_cast<const float4*>(hs + ((size_t)(base + tend)) * DD);
        float4 v = h[tid];
        float cur = ev.x;
        acc.x = fmaf(cur, v.x, acc.x);
        acc.y = fmaf(cur, v.y, acc.y);
        acc.z = fmaf(cur, v.z, acc.z);
        acc.w = fmaf(cur, v.w, acc.w);
        reinterpret_cast<float4*>(out + ((size_t)(base + k)) * DD)[tid] = acc;

        float r = g_alphas[base + tend] - cur;      // resid = a - cur
        acc.x = r * v.x; acc.y = r * v.y; acc.z = r * v.z; acc.w = r * v.w;
        tprev = tend;
    }

    for (int k = klast; k < k0 + KCH; k++)
        reinterpret_cast<float4*>(out + ((size_t)(base + k)) * DD)[tid] = zero;
}

extern "C" void kernel_launch(void* const* d_in, const int* in_sizes, int n_in,
                              void* d_out, int out_size) {
    const float* hs   = (const float*)d_in[0];   // [B,T,D]
    const float* mask = (const float*)d_in[1];   // [B,1,T]
    const float* w    = (const float*)d_in[2];   // [D]
    const float* bias = (const float*)d_in[3];   // scalar

    float* out   = (float*)d_out;                           // [B,T,D]
    float* omask = (float*)d_out + (size_t)BB * TT * DD;    // [B,1,T] as 0/1 floats

    // Fused: alphas (t-chunk-major) + persistent per-batch runner scan
    k_fused<<<NROW / 8, 256>>>(hs, mask, w, bias, omask);
    // Phase 3: KCH output rows per block, reverse-ordered for L2 reuse
    {
        dim3 grid(TT / KCH, BB);
        k_gather<<<grid, 256>>>(hs, out);
    }
}